// round 9
// baseline (speedup 1.0000x reference)
#include <cuda_runtime.h>
#include <cuda_fp16.h>
#include <cstdint>

// ---------------------------------------------------------------- constants
#define OUT_F   4096
#define IN_F    4096
#define KDIM    4096
#define MROWS   8192
#define NBLOCKS (OUT_F * IN_F / 8)        // 2,097,152

// GEMM tiling (fp16 mma.sync m16n8k16, 2-stage x BK=128 ring, persistent CTAs)
#define BM      128
#define BN      256
#define BK      128
#define NITER   (KDIM / BK)               // 32
#define KSTEPS  (BK / 16)                 // 8
#define NTILES  ((MROWS / BM) * (OUT_F / BN))   // 64 * 16 = 1024
#define GRID_P  152                       // persistent CTAs (GB300 = 152 SMs)

#define A_HALF_BYTES  (BM * 128)          // 16 KB
#define B_HALF_BYTES  (BN * 128)          // 32 KB
#define B_BASE_OFF    (2 * A_HALF_BYTES)  // 32 KB
#define STAGE_BYTES   (2 * A_HALF_BYTES + 2 * B_HALF_BYTES)   // 96 KB
#define SMEM_TOTAL    (2 * STAGE_BYTES)                       // 192 KB

__device__ __half g_Wh[(size_t)OUT_F * IN_F];   // 34 MB
__device__ __half g_Xh[(size_t)MROWS * KDIM];   // 67 MB

// ---------------------------------------------------------------- helpers
__device__ __forceinline__ uint32_t smem_u32(const void* p) {
    uint32_t a;
    asm("{ .reg .u64 t; cvta.to.shared.u64 t, %1; cvt.u32.u64 %0, t; }"
        : "=r"(a) : "l"(p));
    return a;
}

#define CP_ASYNC16(sm, gp) \
    asm volatile("cp.async.cg.shared.global [%0], [%1], 16;" :: "r"(sm), "l"(gp) : "memory")
#define CP_COMMIT() asm volatile("cp.async.commit_group;" ::: "memory")
#define CP_WAIT(n)  asm volatile("cp.async.wait_group %0;" :: "n"(n) : "memory")

#define LDMATRIX_X4(r, a) \
    asm volatile("ldmatrix.sync.aligned.m8n8.x4.shared.b16 {%0,%1,%2,%3}, [%4];" \
                 : "=r"((r)[0]), "=r"((r)[1]), "=r"((r)[2]), "=r"((r)[3]) : "r"(a))

__device__ __forceinline__ void mma_f16(float* c, const uint32_t* a, const uint32_t* b) {
    asm volatile(
        "mma.sync.aligned.m16n8k16.row.col.f32.f16.f16.f32 "
        "{%0,%1,%2,%3}, {%4,%5,%6,%7}, {%8,%9}, {%0,%1,%2,%3};"
        : "+f"(c[0]), "+f"(c[1]), "+f"(c[2]), "+f"(c[3])
        : "r"(a[0]), "r"(a[1]), "r"(a[2]), "r"(a[3]),
          "r"(b[0]), "r"(b[1]));
}

// ---------------------------------------------------------------- pre-passes
// Reconstruct W (fp16 rn) with fused block-local index-dtype detection.
// If the index buffer is int64 (LE), odd 32-bit words are hi-halves of values
// < 4096 => zero. 32 samples all-zero => int64; P(false|int32) ~ 4096^-32.
__global__ void k_reconstruct(const void* __restrict__ indices,
                              const float* __restrict__ cb) {
    __shared__ int s_is32;
    const long long B0 = (long long)blockIdx.x * blockDim.x;
    if (threadIdx.x == 0) s_is32 = 0;
    __syncthreads();
    if (threadIdx.x < 32) {
        long long w = (B0 + 2 * threadIdx.x) | 1;
        if (w < NBLOCKS && ((const int*)indices)[w] != 0) s_is32 = 1;
    }
    __syncthreads();

    long long b = B0 + threadIdx.x;
    if (b >= NBLOCKS) return;
    long long v;
    if (s_is32) v = ((const int*)indices)[b];
    else        v = ((const long long*)indices)[b];
    const float4* src = (const float4*)(cb + v * 8);
    float4 lo = src[0], hi = src[1];
    __half2 h[4];
    h[0] = __floats2half2_rn(lo.x, lo.y);
    h[1] = __floats2half2_rn(lo.z, lo.w);
    h[2] = __floats2half2_rn(hi.x, hi.y);
    h[3] = __floats2half2_rn(hi.z, hi.w);
    *(uint4*)(g_Wh + b * 8) = *(uint4*)h;
}

__global__ void k_to_half(const float4* __restrict__ x) {
    size_t i = (size_t)blockIdx.x * blockDim.x + threadIdx.x;
    float4 a = x[2 * i], b = x[2 * i + 1];
    __half2 h[4];
    h[0] = __floats2half2_rn(a.x, a.y);
    h[1] = __floats2half2_rn(a.z, a.w);
    h[2] = __floats2half2_rn(b.x, b.y);
    h[3] = __floats2half2_rn(b.z, b.w);
    *(uint4*)(g_Xh + i * 8) = *(uint4*)h;
}

// ---------------------------------------------------------------- GEMM
__global__ __launch_bounds__(256, 1)
void k_gemm(const float* __restrict__ bias, float* __restrict__ C) {
    extern __shared__ char smem[];
    const uint32_t smem_b = smem_u32(smem);

    const int tid  = threadIdx.x;
    const int lane = tid & 31;
    const int wid  = tid >> 5;
    const int gid  = lane >> 2;
    const int tg   = lane & 3;
    const int wm   = wid & 1;
    const int wn   = wid >> 1;

    // ---- per-thread constant pieces of the fill addressing
    // A ops i=0..3: row rA[i], chunk chA[i]; B ops i=0..7: row rB[i], chunk chB[i]
    int rA[4], chA[4], rB[8], chB[8];
    uint32_t sOff[24];                 // smem offset within stage (constant)
    #pragma unroll
    for (int i = 0; i < 4; i++) {
        int v = tid + i * 256;
        rA[i] = v >> 3; chA[i] = v & 7;
        uint32_t so = (uint32_t)(rA[i] * 128 + ((chA[i] ^ (rA[i] & 7)) << 4));
        sOff[0 + i] = so;                       // k-half 0
        sOff[4 + i] = A_HALF_BYTES + so;        // k-half 1
    }
    #pragma unroll
    for (int i = 0; i < 8; i++) {
        int v = tid + i * 256;
        rB[i] = v >> 3; chB[i] = v & 7;
        uint32_t so = (uint32_t)(B_BASE_OFF + rB[i] * 128 + ((chB[i] ^ (rB[i] & 7)) << 4));
        sOff[8 + i]  = so;                      // k-half 0
        sOff[16 + i] = B_HALF_BYTES + so;       // k-half 1
    }

    // gPtr: global source base per fill op (retargeted per tile)
    const __half* gPtr[24];
    auto set_gptr = [&](int m0t, int n0t) {
        #pragma unroll
        for (int i = 0; i < 4; i++) {
            const __half* gp = g_Xh + (size_t)(m0t + rA[i]) * KDIM + chA[i] * 8;
            gPtr[0 + i] = gp;
            gPtr[4 + i] = gp + 64;
        }
        #pragma unroll
        for (int i = 0; i < 8; i++) {
            const __half* gp = g_Wh + (size_t)(n0t + rB[i]) * KDIM + chB[i] * 8;
            gPtr[8 + i]  = gp;
            gPtr[16 + i] = gp + 64;
        }
    };

    // ---- ldmatrix per-lane bases
    const int row_off = lane & 7;
    const int a_kb = lane >> 4;
    const int b_kb = (lane >> 3) & 1;
    uint32_t aoff[4], boff[4];
    #pragma unroll
    for (int mf = 0; mf < 4; mf++)
        aoff[mf] = (uint32_t)((wm * 64 + mf * 16 + row_off + ((lane >> 3) & 1) * 8) * 128);
    #pragma unroll
    for (int p = 0; p < 4; p++)
        boff[p] = (uint32_t)((wn * 64 + p * 16 + ((lane >> 4) & 1) * 8 + row_off) * 128);

    float acc[4][8][4];
    #pragma unroll
    for (int mf = 0; mf < 4; mf++)
        #pragma unroll
        for (int nf = 0; nf < 8; nf++)
            #pragma unroll
            for (int r = 0; r < 4; r++) acc[mf][nf][r] = 0.f;

    uint32_t a_frag[2][4][4];
    uint32_t b_frag[2][4][4];

    // ---- persistent tile loop
    int tile = blockIdx.x;
    {   // prologue: fill stage 0 of first tile
        set_gptr((tile >> 4) * BM, (tile & 15) * BN);
        #pragma unroll
        for (int o = 0; o < 24; o++) CP_ASYNC16(smem_b + sOff[o], gPtr[o]);
        CP_COMMIT();
    }

    while (tile < NTILES) {
        const int m0 = (tile >> 4) * BM;
        const int n0 = (tile & 15) * BN;
        const int next_tile = tile + GRID_P;

        for (int it = 0; it < NITER; it++) {
            const int s = it & 1;
            const uint32_t stage  = smem_b + s * STAGE_BYTES;
            const uint32_t nstage = smem_b + (s ^ 1) * STAGE_BYTES;

            CP_WAIT(0);
            __syncthreads();

            // at the last iter, retarget fills to next tile's stage 0
            int knext;
            bool do_fill;
            if (it < NITER - 1) {
                knext = (it + 1) * BK;
                do_fill = true;
            } else {
                knext = 0;
                do_fill = (next_tile < NTILES);
                if (do_fill) set_gptr((next_tile >> 4) * BM, (next_tile & 15) * BN);
            }

            // preload ks=0 fragments
            {
                const uint32_t ac = (uint32_t)((a_kb ^ row_off) << 4);
                const uint32_t bc = (uint32_t)((b_kb ^ row_off) << 4);
                #pragma unroll
                for (int mf = 0; mf < 4; mf++) LDMATRIX_X4(a_frag[0][mf], stage + aoff[mf] + ac);
                #pragma unroll
                for (int p = 0; p < 4; p++)
                    LDMATRIX_X4(b_frag[0][p], stage + B_BASE_OFF + boff[p] + bc);
            }

            #pragma unroll
            for (int ks = 0; ks < KSTEPS; ks++) {
                const int cur = ks & 1;
                // spread fill over first 6 k-steps: 4 ops each -> ~2 k-steps slack
                if (do_fill && ks < 6) {
                    #pragma unroll
                    for (int j = 0; j < 4; j++) {
                        const int o = ks * 4 + j;
                        CP_ASYNC16(nstage + sOff[o], gPtr[o] + knext);
                    }
                }
                if (ks + 1 < KSTEPS) {
                    const int nb  = cur ^ 1;
                    const int kn  = ks + 1;
                    const int kh  = kn >> 2;
                    const int kk  = kn & 3;
                    const uint32_t abase = stage + kh * A_HALF_BYTES;
                    const uint32_t bbase = stage + B_BASE_OFF + kh * B_HALF_BYTES;
                    const uint32_t ac = (uint32_t)((((2 * kk) | a_kb) ^ row_off) << 4);
                    const uint32_t bc = (uint32_t)((((2 * kk) | b_kb) ^ row_off) << 4);
                    #pragma unroll
                    for (int mf = 0; mf < 4; mf++) LDMATRIX_X4(a_frag[nb][mf], abase + aoff[mf] + ac);
                    #pragma unroll
                    for (int p = 0; p < 4; p++)    LDMATRIX_X4(b_frag[nb][p],  bbase + boff[p]  + bc);
                }
                #pragma unroll
                for (int mf = 0; mf < 4; mf++)
                    #pragma unroll
                    for (int p = 0; p < 4; p++) {
                        mma_f16(acc[mf][2 * p],     a_frag[cur][mf], &b_frag[cur][p][0]);
                        mma_f16(acc[mf][2 * p + 1], a_frag[cur][mf], &b_frag[cur][p][2]);
                    }
            }
            CP_COMMIT();
        }

        // ---- epilogue: bias + store + reset (overlaps next tile's fill)
        const int mbase = m0 + wm * 64;
        const int nbase = n0 + wn * 64;
        #pragma unroll
        for (int nf = 0; nf < 8; nf++) {
            const int cc = nbase + nf * 8 + 2 * tg;
            const float bv0 = __ldg(bias + cc);
            const float bv1 = __ldg(bias + cc + 1);
            #pragma unroll
            for (int mf = 0; mf < 4; mf++) {
                const int r = mbase + mf * 16 + gid;
                float2 v0 = make_float2(acc[mf][nf][0] + bv0, acc[mf][nf][1] + bv1);
                float2 v1 = make_float2(acc[mf][nf][2] + bv0, acc[mf][nf][3] + bv1);
                *(float2*)(C + (size_t)r * OUT_F + cc)       = v0;
                *(float2*)(C + (size_t)(r + 8) * OUT_F + cc) = v1;
                acc[mf][nf][0] = 0.f; acc[mf][nf][1] = 0.f;
                acc[mf][nf][2] = 0.f; acc[mf][nf][3] = 0.f;
            }
        }
        tile = next_tile;
    }
}

// ---------------------------------------------------------------- launch
extern "C" void kernel_launch(void* const* d_in, const int* in_sizes, int n_in,
                              void* d_out, int out_size) {
    const float* x    = (const float*)d_in[0];   // [4,2048,4096]
    const float* cb   = (const float*)d_in[1];   // [4096,8]
    const void*  idx  = d_in[2];                 // [NBLOCKS] int32 or int64
    const float* bias = (const float*)d_in[3];   // [4096]
    float* out = (float*)d_out;

    {
        size_t n8 = (size_t)MROWS * KDIM / 8;
        k_to_half<<<(int)((n8 + 255) / 256), 256>>>((const float4*)x);
    }
    k_reconstruct<<<(NBLOCKS + 255) / 256, 256>>>(idx, cb);

    cudaFuncSetAttribute(k_gemm, cudaFuncAttributeMaxDynamicSharedMemorySize, SMEM_TOTAL);
    k_gemm<<<GRID_P, 256, SMEM_TOTAL>>>(bias, out);
}

// round 10
// speedup vs baseline: 1.0218x; 1.0218x over previous
#include <cuda_runtime.h>
#include <cuda_fp16.h>
#include <cstdint>

// ---------------------------------------------------------------- constants
#define OUT_F   4096
#define IN_F    4096
#define KDIM    4096
#define MROWS   8192
#define NBLOCKS (OUT_F * IN_F / 8)        // 2,097,152

// GEMM tiling (fp16 mma.sync m16n8k16, 2-stage x BK=128 cp.async ring)
#define BM      128
#define BN      256
#define BK      128
#define NITER   (KDIM / BK)               // 32
#define KSTEPS  (BK / 16)                 // 8

#define A_HALF_BYTES  (BM * 128)          // 16 KB
#define B_HALF_BYTES  (BN * 128)          // 32 KB
#define B_BASE_OFF    (2 * A_HALF_BYTES)  // 32 KB
#define STAGE_BYTES   (2 * A_HALF_BYTES + 2 * B_HALF_BYTES)   // 96 KB
#define SMEM_TOTAL    (2 * STAGE_BYTES)                       // 192 KB

// merged pre-pass grid: every 5th CTA reconstructs W, the rest convert X
#define REC_CTAS   4096                   // x 512 blocks = NBLOCKS
#define CVT_CTAS   16384                  // x 2048 floats = MROWS*KDIM
#define PRE_GRID   (REC_CTAS + CVT_CTAS)  // 20480

__device__ __half g_Wh[(size_t)OUT_F * IN_F];   // 34 MB
__device__ __half g_Xh[(size_t)MROWS * KDIM];   // 67 MB

// ---------------------------------------------------------------- helpers
__device__ __forceinline__ uint32_t smem_u32(const void* p) {
    uint32_t a;
    asm("{ .reg .u64 t; cvta.to.shared.u64 t, %1; cvt.u32.u64 %0, t; }"
        : "=r"(a) : "l"(p));
    return a;
}

#define CP_ASYNC16(sm, gp) \
    asm volatile("cp.async.cg.shared.global [%0], [%1], 16;" :: "r"(sm), "l"(gp) : "memory")
#define CP_COMMIT() asm volatile("cp.async.commit_group;" ::: "memory")
#define CP_WAIT(n)  asm volatile("cp.async.wait_group %0;" :: "n"(n) : "memory")

#define LDMATRIX_X4(r, a) \
    asm volatile("ldmatrix.sync.aligned.m8n8.x4.shared.b16 {%0,%1,%2,%3}, [%4];" \
                 : "=r"((r)[0]), "=r"((r)[1]), "=r"((r)[2]), "=r"((r)[3]) : "r"(a))

__device__ __forceinline__ void mma_f16(float* c, const uint32_t* a, const uint32_t* b) {
    asm volatile(
        "mma.sync.aligned.m16n8k16.row.col.f32.f16.f16.f32 "
        "{%0,%1,%2,%3}, {%4,%5,%6,%7}, {%8,%9}, {%0,%1,%2,%3};"
        : "+f"(c[0]), "+f"(c[1]), "+f"(c[2]), "+f"(c[3])
        : "r"(a[0]), "r"(a[1]), "r"(a[2]), "r"(a[3]),
          "r"(b[0]), "r"(b[1]));
}

// ---------------------------------------------------------------- merged pre-pass
// bid % 5 == 4  -> reconstruct slice r = bid/5   (4096 slices x 512 blocks)
// else          -> convert slice    t = (bid/5)*4 + bid%5  (16384 slices)
// Striping interleaves the DRAM-streaming convert with the gather-bound
// reconstruct in every wave, using both pipes concurrently.
__global__ void k_prepass(const float4* __restrict__ x,
                          const void* __restrict__ indices,
                          const float* __restrict__ cb) {
    const int bid = blockIdx.x;
    const int q = bid / 5, rm = bid - q * 5;

    if (rm == 4) {
        // ---- reconstruct: 512 codebook blocks, 2 per thread
        const long long B0 = (long long)q * 512;
        __shared__ int s_is32;
        if (threadIdx.x == 0) s_is32 = 0;
        __syncthreads();
        if (threadIdx.x < 32) {
            // odd 32-bit words of an int64 buffer here are hi-halves of
            // values < 4096 => all zero. int32 random indices: ~never.
            long long w = (B0 + 2 * threadIdx.x) | 1;
            if (((const int*)indices)[w] != 0) s_is32 = 1;
        }
        __syncthreads();
        const bool is32 = s_is32 != 0;

        long long b = B0 + threadIdx.x * 2;
        long long v0, v1;
        if (is32) {
            v0 = ((const int*)indices)[b];
            v1 = ((const int*)indices)[b + 1];
        } else {
            v0 = ((const long long*)indices)[b];
            v1 = ((const long long*)indices)[b + 1];
        }
        const float4* s0 = (const float4*)(cb + v0 * 8);
        const float4* s1 = (const float4*)(cb + v1 * 8);
        float4 a0 = s0[0], a1 = s0[1], c0 = s1[0], c1 = s1[1];
        __half2 h[8];
        h[0] = __floats2half2_rn(a0.x, a0.y);
        h[1] = __floats2half2_rn(a0.z, a0.w);
        h[2] = __floats2half2_rn(a1.x, a1.y);
        h[3] = __floats2half2_rn(a1.z, a1.w);
        h[4] = __floats2half2_rn(c0.x, c0.y);
        h[5] = __floats2half2_rn(c0.z, c0.w);
        h[6] = __floats2half2_rn(c1.x, c1.y);
        h[7] = __floats2half2_rn(c1.z, c1.w);
        uint4* dst = (uint4*)(g_Wh + b * 8);
        dst[0] = ((uint4*)h)[0];
        dst[1] = ((uint4*)h)[1];
    } else {
        // ---- convert: 2048 floats per CTA, 8 per thread
        const size_t t = (size_t)q * 4 + rm;
        const size_t i = t * 256 + threadIdx.x;
        float4 a = x[2 * i], b = x[2 * i + 1];
        __half2 h[4];
        h[0] = __floats2half2_rn(a.x, a.y);
        h[1] = __floats2half2_rn(a.z, a.w);
        h[2] = __floats2half2_rn(b.x, b.y);
        h[3] = __floats2half2_rn(b.z, b.w);
        *(uint4*)(g_Xh + i * 8) = *(uint4*)h;
    }
}

// ---------------------------------------------------------------- GEMM (R8 form)
__global__ __launch_bounds__(256, 1)
void k_gemm(const float* __restrict__ bias, float* __restrict__ C) {
    extern __shared__ char smem[];
    const uint32_t smem_b = smem_u32(smem);

    const int tid  = threadIdx.x;
    const int lane = tid & 31;
    const int wid  = tid >> 5;
    const int gid  = lane >> 2;
    const int tg   = lane & 3;
    const int wm   = wid & 1;
    const int wn   = wid >> 1;

    const int m0 = blockIdx.y * BM;
    const int n0 = blockIdx.x * BN;

    // ---- fill op table: 24 x 16B cp.async per thread per stage
    uint32_t sOff[24];
    const __half* gPtr[24];
    #pragma unroll
    for (int i = 0; i < 4; i++) {
        int v = tid + i * 256, r = v >> 3, ch = v & 7;
        uint32_t so = (uint32_t)(r * 128 + ((ch ^ (r & 7)) << 4));
        const __half* gp = g_Xh + (size_t)(m0 + r) * KDIM + ch * 8;
        #pragma unroll
        for (int kh = 0; kh < 2; kh++) {
            sOff[kh * 4 + i] = kh * A_HALF_BYTES + so;
            gPtr[kh * 4 + i] = gp + kh * 64;
        }
    }
    #pragma unroll
    for (int i = 0; i < 8; i++) {
        int v = tid + i * 256, r = v >> 3, ch = v & 7;
        uint32_t so = (uint32_t)(B_BASE_OFF + r * 128 + ((ch ^ (r & 7)) << 4));
        const __half* gp = g_Wh + (size_t)(n0 + r) * KDIM + ch * 8;
        #pragma unroll
        for (int kh = 0; kh < 2; kh++) {
            sOff[8 + kh * 8 + i] = kh * B_HALF_BYTES + so;
            gPtr[8 + kh * 8 + i] = gp + kh * 64;
        }
    }

    // ---- ldmatrix per-lane bases
    const int row_off = lane & 7;
    const int a_kb = lane >> 4;
    const int b_kb = (lane >> 3) & 1;
    uint32_t aoff[4], boff[4];
    #pragma unroll
    for (int mf = 0; mf < 4; mf++)
        aoff[mf] = (uint32_t)((wm * 64 + mf * 16 + row_off + ((lane >> 3) & 1) * 8) * 128);
    #pragma unroll
    for (int p = 0; p < 4; p++)
        boff[p] = (uint32_t)((wn * 64 + p * 16 + ((lane >> 4) & 1) * 8 + row_off) * 128);

    // ---- prefill stage 0
    #pragma unroll
    for (int o = 0; o < 24; o++) CP_ASYNC16(smem_b + sOff[o], gPtr[o]);
    CP_COMMIT();

    float acc[4][8][4];
    #pragma unroll
    for (int mf = 0; mf < 4; mf++)
        #pragma unroll
        for (int nf = 0; nf < 8; nf++)
            #pragma unroll
            for (int r = 0; r < 4; r++) acc[mf][nf][r] = 0.f;

    uint32_t a_frag[2][4][4];
    uint32_t b_frag[2][4][4];

    for (int it = 0; it < NITER; it++) {
        const int s = it & 1;
        const uint32_t stage = smem_b + s * STAGE_BYTES;
        const uint32_t nstage = smem_b + (s ^ 1) * STAGE_BYTES;
        const int knext = (it + 1) * BK;
        const bool do_fill = (it + 1 < NITER);

        CP_WAIT(0);
        __syncthreads();

        // preload ks=0 fragments
        {
            const uint32_t ac = (uint32_t)((a_kb ^ row_off) << 4);
            const uint32_t bc = (uint32_t)((b_kb ^ row_off) << 4);
            #pragma unroll
            for (int mf = 0; mf < 4; mf++) LDMATRIX_X4(a_frag[0][mf], stage + aoff[mf] + ac);
            #pragma unroll
            for (int p = 0; p < 4; p++)
                LDMATRIX_X4(b_frag[0][p], stage + B_BASE_OFF + boff[p] + bc);
        }

        #pragma unroll
        for (int ks = 0; ks < KSTEPS; ks++) {
            const int cur = ks & 1;
            if (do_fill) {
                #pragma unroll
                for (int j = 0; j < 3; j++) {
                    const int o = ks * 3 + j;
                    CP_ASYNC16(nstage + sOff[o], gPtr[o] + knext);
                }
            }
            if (ks + 1 < KSTEPS) {
                const int nb  = cur ^ 1;
                const int kn  = ks + 1;
                const int kh  = kn >> 2;
                const int kk  = kn & 3;
                const uint32_t abase = stage + kh * A_HALF_BYTES;
                const uint32_t bbase = stage + B_BASE_OFF + kh * B_HALF_BYTES;
                const uint32_t ac = (uint32_t)((((2 * kk) | a_kb) ^ row_off) << 4);
                const uint32_t bc = (uint32_t)((((2 * kk) | b_kb) ^ row_off) << 4);
                #pragma unroll
                for (int mf = 0; mf < 4; mf++) LDMATRIX_X4(a_frag[nb][mf], abase + aoff[mf] + ac);
                #pragma unroll
                for (int p = 0; p < 4; p++)    LDMATRIX_X4(b_frag[nb][p],  bbase + boff[p]  + bc);
            }
            #pragma unroll
            for (int mf = 0; mf < 4; mf++)
                #pragma unroll
                for (int p = 0; p < 4; p++) {
                    mma_f16(acc[mf][2 * p],     a_frag[cur][mf], &b_frag[cur][p][0]);
                    mma_f16(acc[mf][2 * p + 1], a_frag[cur][mf], &b_frag[cur][p][2]);
                }
        }
        CP_COMMIT();
    }

    // ---- epilogue: bias + store
    const int mbase = m0 + wm * 64;
    const int nbase = n0 + wn * 64;
    #pragma unroll
    for (int nf = 0; nf < 8; nf++) {
        const int cc = nbase + nf * 8 + 2 * tg;
        const float bv0 = __ldg(bias + cc);
        const float bv1 = __ldg(bias + cc + 1);
        #pragma unroll
        for (int mf = 0; mf < 4; mf++) {
            const int r = mbase + mf * 16 + gid;
            float2 v0 = make_float2(acc[mf][nf][0] + bv0, acc[mf][nf][1] + bv1);
            float2 v1 = make_float2(acc[mf][nf][2] + bv0, acc[mf][nf][3] + bv1);
            *(float2*)(C + (size_t)r * OUT_F + cc)       = v0;
            *(float2*)(C + (size_t)(r + 8) * OUT_F + cc) = v1;
        }
    }
}

// ---------------------------------------------------------------- launch
extern "C" void kernel_launch(void* const* d_in, const int* in_sizes, int n_in,
                              void* d_out, int out_size) {
    const float* x    = (const float*)d_in[0];   // [4,2048,4096]
    const float* cb   = (const float*)d_in[1];   // [4096,8]
    const void*  idx  = d_in[2];                 // [NBLOCKS] int32 or int64
    const float* bias = (const float*)d_in[3];   // [4096]
    float* out = (float*)d_out;

    k_prepass<<<PRE_GRID, 256>>>((const float4*)x, idx, cb);

    cudaFuncSetAttribute(k_gemm, cudaFuncAttributeMaxDynamicSharedMemorySize, SMEM_TOTAL);
    dim3 grid(OUT_F / BN, MROWS / BM);   // (16, 64)
    k_gemm<<<grid, 256, SMEM_TOTAL>>>(bias, out);
}

// round 12
// speedup vs baseline: 1.0862x; 1.0630x over previous
#include <cuda_runtime.h>
#include <cuda_fp16.h>
#include <cstdint>

// ---------------------------------------------------------------- constants
#define OUT_F   4096
#define IN_F    4096
#define KDIM    4096
#define MROWS   8192
#define NBLOCKS (OUT_F * IN_F / 8)        // 2,097,152

// GEMM tiling (fp16 mma.sync m16n8k16, 2-stage x BK=128 cp.async ring)
#define BM      128
#define BN      256
#define BK      128
#define NITER   (KDIM / BK)               // 32
#define KSTEPS  (BK / 16)                 // 8

#define A_HALF_BYTES  (BM * 128)          // 16 KB
#define B_HALF_BYTES  (BN * 128)          // 32 KB
#define B_BASE_OFF    (2 * A_HALF_BYTES)  // 32 KB
#define STAGE_BYTES   (2 * A_HALF_BYTES + 2 * B_HALF_BYTES)   // 96 KB
#define SMEM_TOTAL    (2 * STAGE_BYTES)                       // 192 KB

// merged pre-pass grid: every 5th CTA reconstructs W, the rest convert X
#define REC_CTAS   4096                   // x 512 blocks = NBLOCKS
#define CVT_CTAS   16384                  // x 2048 floats = MROWS*KDIM
#define PRE_GRID   (REC_CTAS + CVT_CTAS)  // 20480

__device__ __half g_Wh[(size_t)OUT_F * IN_F];   // 34 MB
__device__ __half g_Xh[(size_t)MROWS * KDIM];   // 67 MB

// ---------------------------------------------------------------- helpers
__device__ __forceinline__ uint32_t smem_u32(const void* p) {
    uint32_t a;
    asm("{ .reg .u64 t; cvta.to.shared.u64 t, %1; cvt.u32.u64 %0, t; }"
        : "=r"(a) : "l"(p));
    return a;
}

#define CP_ASYNC16(sm, gp) \
    asm volatile("cp.async.cg.shared.global [%0], [%1], 16;" :: "r"(sm), "l"(gp) : "memory")
#define CP_COMMIT() asm volatile("cp.async.commit_group;" ::: "memory")
#define CP_WAIT(n)  asm volatile("cp.async.wait_group %0;" :: "n"(n) : "memory")

#define LDMATRIX_X4(r, a) \
    asm volatile("ldmatrix.sync.aligned.m8n8.x4.shared.b16 {%0,%1,%2,%3}, [%4];" \
                 : "=r"((r)[0]), "=r"((r)[1]), "=r"((r)[2]), "=r"((r)[3]) : "r"(a))

__device__ __forceinline__ void mma_f16(float* c, const uint32_t* a, const uint32_t* b) {
    asm volatile(
        "mma.sync.aligned.m16n8k16.row.col.f32.f16.f16.f32 "
        "{%0,%1,%2,%3}, {%4,%5,%6,%7}, {%8,%9}, {%0,%1,%2,%3};"
        : "+f"(c[0]), "+f"(c[1]), "+f"(c[2]), "+f"(c[3])
        : "r"(a[0]), "r"(a[1]), "r"(a[2]), "r"(a[3]),
          "r"(b[0]), "r"(b[1]));
}

// ---------------------------------------------------------------- merged pre-pass
__global__ void k_prepass(const float4* __restrict__ x,
                          const void* __restrict__ indices,
                          const float* __restrict__ cb) {
    const int bid = blockIdx.x;
    const int q = bid / 5, rm = bid - q * 5;

    if (rm == 4) {
        // ---- reconstruct: 512 codebook blocks, 2 per thread
        const long long B0 = (long long)q * 512;
        __shared__ int s_is32;
        if (threadIdx.x == 0) s_is32 = 0;
        __syncthreads();
        if (threadIdx.x < 32) {
            // odd 32-bit words of an int64 buffer here are hi-halves of
            // values < 4096 => all zero. int32 random indices: ~never.
            long long w = (B0 + 2 * threadIdx.x) | 1;
            if (((const int*)indices)[w] != 0) s_is32 = 1;
        }
        __syncthreads();
        const bool is32 = s_is32 != 0;

        long long b = B0 + threadIdx.x * 2;
        long long v0, v1;
        if (is32) {
            v0 = ((const int*)indices)[b];
            v1 = ((const int*)indices)[b + 1];
        } else {
            v0 = ((const long long*)indices)[b];
            v1 = ((const long long*)indices)[b + 1];
        }
        const float4* s0 = (const float4*)(cb + v0 * 8);
        const float4* s1 = (const float4*)(cb + v1 * 8);
        float4 a0 = s0[0], a1 = s0[1], c0 = s1[0], c1 = s1[1];
        __half2 h[8];
        h[0] = __floats2half2_rn(a0.x, a0.y);
        h[1] = __floats2half2_rn(a0.z, a0.w);
        h[2] = __floats2half2_rn(a1.x, a1.y);
        h[3] = __floats2half2_rn(a1.z, a1.w);
        h[4] = __floats2half2_rn(c0.x, c0.y);
        h[5] = __floats2half2_rn(c0.z, c0.w);
        h[6] = __floats2half2_rn(c1.x, c1.y);
        h[7] = __floats2half2_rn(c1.z, c1.w);
        uint4* dst = (uint4*)(g_Wh + b * 8);
        dst[0] = ((uint4*)h)[0];
        dst[1] = ((uint4*)h)[1];
    } else {
        // ---- convert: 2048 floats per CTA, 8 per thread
        const size_t t = (size_t)q * 4 + rm;
        const size_t i = t * 256 + threadIdx.x;
        float4 a = x[2 * i], b = x[2 * i + 1];
        __half2 h[4];
        h[0] = __floats2half2_rn(a.x, a.y);
        h[1] = __floats2half2_rn(a.z, a.w);
        h[2] = __floats2half2_rn(b.x, b.y);
        h[3] = __floats2half2_rn(b.z, b.w);
        *(uint4*)(g_Xh + i * 8) = *(uint4*)h;
    }
}

// ---------------------------------------------------------------- GEMM
__global__ __launch_bounds__(256, 1)
void k_gemm(const float* __restrict__ bias, float* __restrict__ C) {
    extern __shared__ char smem[];
    const uint32_t smem_b = smem_u32(smem);

    const int tid  = threadIdx.x;
    const int lane = tid & 31;
    const int wid  = tid >> 5;
    const int gid  = lane >> 2;
    const int tg   = lane & 3;
    const int wm   = wid & 1;
    const int wn   = wid >> 1;

    const int m0 = blockIdx.y * BM;
    const int n0 = blockIdx.x * BN;

    // ---- fill op table: 24 x 16B cp.async per thread per stage
    uint32_t sOff[24];
    const __half* gPtr[24];
    #pragma unroll
    for (int i = 0; i < 4; i++) {
        int v = tid + i * 256, r = v >> 3, ch = v & 7;
        uint32_t so = (uint32_t)(r * 128 + ((ch ^ (r & 7)) << 4));
        const __half* gp = g_Xh + (size_t)(m0 + r) * KDIM + ch * 8;
        #pragma unroll
        for (int kh = 0; kh < 2; kh++) {
            sOff[kh * 4 + i] = kh * A_HALF_BYTES + so;
            gPtr[kh * 4 + i] = gp + kh * 64;
        }
    }
    #pragma unroll
    for (int i = 0; i < 8; i++) {
        int v = tid + i * 256, r = v >> 3, ch = v & 7;
        uint32_t so = (uint32_t)(B_BASE_OFF + r * 128 + ((ch ^ (r & 7)) << 4));
        const __half* gp = g_Wh + (size_t)(n0 + r) * KDIM + ch * 8;
        #pragma unroll
        for (int kh = 0; kh < 2; kh++) {
            sOff[8 + kh * 8 + i] = kh * B_HALF_BYTES + so;
            gPtr[8 + kh * 8 + i] = gp + kh * 64;
        }
    }

    // ---- ldmatrix per-lane bases
    const int row_off = lane & 7;
    const int a_kb = lane >> 4;
    const int b_kb = (lane >> 3) & 1;
    uint32_t aoff[4], boff[4];
    #pragma unroll
    for (int mf = 0; mf < 4; mf++)
        aoff[mf] = (uint32_t)((wm * 64 + mf * 16 + row_off + ((lane >> 3) & 1) * 8) * 128);
    #pragma unroll
    for (int p = 0; p < 4; p++)
        boff[p] = (uint32_t)((wn * 64 + p * 16 + ((lane >> 4) & 1) * 8 + row_off) * 128);

    // ---- prefill stage 0
    #pragma unroll
    for (int o = 0; o < 24; o++) CP_ASYNC16(smem_b + sOff[o], gPtr[o]);
    CP_COMMIT();

    // ---- prefetch bias into registers (overlaps prologue fill latency)
    const int nbase = n0 + wn * 64;
    float bv[8][2];
    #pragma unroll
    for (int nf = 0; nf < 8; nf++) {
        const int cc = nbase + nf * 8 + 2 * tg;
        bv[nf][0] = __ldg(bias + cc);
        bv[nf][1] = __ldg(bias + cc + 1);
    }

    float acc[4][8][4];
    #pragma unroll
    for (int mf = 0; mf < 4; mf++)
        #pragma unroll
        for (int nf = 0; nf < 8; nf++)
            #pragma unroll
            for (int r = 0; r < 4; r++) acc[mf][nf][r] = 0.f;

    uint32_t a_frag[2][4][4];
    uint32_t b_frag[2][4][4];

    for (int it = 0; it < NITER; it++) {
        const int s = it & 1;
        const uint32_t stage = smem_b + s * STAGE_BYTES;
        const uint32_t nstage = smem_b + (s ^ 1) * STAGE_BYTES;
        const int knext = (it + 1) * BK;
        const bool do_fill = (it + 1 < NITER);

        CP_WAIT(0);
        __syncthreads();

        // preload ks=0 fragments
        {
            const uint32_t ac = (uint32_t)((a_kb ^ row_off) << 4);
            const uint32_t bc = (uint32_t)((b_kb ^ row_off) << 4);
            #pragma unroll
            for (int mf = 0; mf < 4; mf++) LDMATRIX_X4(a_frag[0][mf], stage + aoff[mf] + ac);
            #pragma unroll
            for (int p = 0; p < 4; p++)
                LDMATRIX_X4(b_frag[0][p], stage + B_BASE_OFF + boff[p] + bc);
        }

        #pragma unroll
        for (int ks = 0; ks < KSTEPS; ks++) {
            const int cur = ks & 1;
            // fill 4 ops/k-step over ks=0..5; commit right away at ks==5 so the
            // group ages >= 2 k-steps before the next iteration's wait
            if (do_fill && ks < 6) {
                #pragma unroll
                for (int j = 0; j < 4; j++) {
                    const int o = ks * 4 + j;
                    CP_ASYNC16(nstage + sOff[o], gPtr[o] + knext);
                }
                if (ks == 5) CP_COMMIT();
            }
            if (ks + 1 < KSTEPS) {
                const int nb  = cur ^ 1;
                const int kn  = ks + 1;
                const int kh  = kn >> 2;
                const int kk  = kn & 3;
                const uint32_t abase = stage + kh * A_HALF_BYTES;
                const uint32_t bbase = stage + B_BASE_OFF + kh * B_HALF_BYTES;
                const uint32_t ac = (uint32_t)((((2 * kk) | a_kb) ^ row_off) << 4);
                const uint32_t bc = (uint32_t)((((2 * kk) | b_kb) ^ row_off) << 4);
                #pragma unroll
                for (int mf = 0; mf < 4; mf++) LDMATRIX_X4(a_frag[nb][mf], abase + aoff[mf] + ac);
                #pragma unroll
                for (int p = 0; p < 4; p++)    LDMATRIX_X4(b_frag[nb][p],  bbase + boff[p]  + bc);
            }
            #pragma unroll
            for (int mf = 0; mf < 4; mf++)
                #pragma unroll
                for (int p = 0; p < 4; p++) {
                    mma_f16(acc[mf][2 * p],     a_frag[cur][mf], &b_frag[cur][p][0]);
                    mma_f16(acc[mf][2 * p + 1], a_frag[cur][mf], &b_frag[cur][p][2]);
                }
        }
        if (!do_fill) CP_COMMIT();   // keep group accounting balanced on last iter
    }

    // ---- epilogue: bias + store (bias already in registers)
    const int mbase = m0 + wm * 64;
    #pragma unroll
    for (int nf = 0; nf < 8; nf++) {
        const int cc = nbase + nf * 8 + 2 * tg;
        #pragma unroll
        for (int mf = 0; mf < 4; mf++) {
            const int r = mbase + mf * 16 + gid;
            float2 v0 = make_float2(acc[mf][nf][0] + bv[nf][0], acc[mf][nf][1] + bv[nf][1]);
            float2 v1 = make_float2(acc[mf][nf][2] + bv[nf][0], acc[mf][nf][3] + bv[nf][1]);
            *(float2*)(C + (size_t)r * OUT_F + cc)       = v0;
            *(float2*)(C + (size_t)(r + 8) * OUT_F + cc) = v1;
        }
    }
}

// ---------------------------------------------------------------- launch
extern "C" void kernel_launch(void* const* d_in, const int* in_sizes, int n_in,
                              void* d_out, int out_size) {
    const float* x    = (const float*)d_in[0];   // [4,2048,4096]
    const float* cb   = (const float*)d_in[1];   // [4096,8]
    const void*  idx  = d_in[2];                 // [NBLOCKS] int32 or int64
    const float* bias = (const float*)d_in[3];   // [4096]
    float* out = (float*)d_out;

    k_prepass<<<PRE_GRID, 256>>>((const float4*)x, idx, cb);

    cudaFuncSetAttribute(k_gemm, cudaFuncAttributeMaxDynamicSharedMemorySize, SMEM_TOTAL);
    dim3 grid(OUT_F / BN, MROWS / BM);   // (16, 64)
    k_gemm<<<grid, 256, SMEM_TOTAL>>>(bias, out);
}